// round 15
// baseline (speedup 1.0000x reference)
#include <cuda_runtime.h>
#include <cuda_bf16.h>
#include <cfloat>

typedef __nv_bfloat16 bf16;

// Problem dims
constexpr int BZ = 8, LQ = 2048, LKV = 512, H = 1024, H2 = 2048, NH = 16, DH = 64, BH = BZ * NH;
constexpr size_t NQ  = (size_t)BZ * LQ * H;
constexpr size_t NKV = (size_t)BZ * LKV * H;

// Scratch (device globals: allocation-free per harness rules)
__device__ bf16  g_xq[NQ];
__device__ bf16  g_xkv[NKV];
__device__ bf16  g_q[NQ];
__device__ bf16  g_kv[2 * NKV];
__device__ bf16  g_ao[NQ];
__device__ bf16  g_wq[H * H];      // transposed: [N=H, K=H]
__device__ bf16  g_wkv[H2 * H];    // transposed: [N=2H, K=H]
__device__ bf16  g_wp[H * H];      // transposed
__device__ float g_ssq[BZ * H2];
__device__ float g_sskv[BZ * H2];

// ---------------- low-level helpers ----------------
__device__ __forceinline__ unsigned smem_u32(const void* p) {
    return (unsigned)__cvta_generic_to_shared(p);
}
__device__ __forceinline__ void cp16(void* s, const void* g) {
    unsigned sa = smem_u32(s);
    asm volatile("cp.async.cg.shared.global [%0], [%1], 16;\n" :: "r"(sa), "l"(g));
}
#define CP_COMMIT()  asm volatile("cp.async.commit_group;\n")
#define CP_WAIT(N)   asm volatile("cp.async.wait_group %0;\n" :: "n"(N))

__device__ __forceinline__ unsigned sw128(unsigned x) { return x ^ ((x >> 3) & 0x70); }

__device__ __forceinline__ void ldsm_x4(unsigned& r0, unsigned& r1, unsigned& r2, unsigned& r3,
                                        unsigned addr) {
    asm volatile("ldmatrix.sync.aligned.m8n8.x4.shared.b16 {%0,%1,%2,%3}, [%4];"
                 : "=r"(r0), "=r"(r1), "=r"(r2), "=r"(r3) : "r"(addr));
}
__device__ __forceinline__ void ldsm_x4t(unsigned& r0, unsigned& r1, unsigned& r2, unsigned& r3,
                                         unsigned addr) {
    asm volatile("ldmatrix.sync.aligned.m8n8.x4.trans.shared.b16 {%0,%1,%2,%3}, [%4];"
                 : "=r"(r0), "=r"(r1), "=r"(r2), "=r"(r3) : "r"(addr));
}
__device__ __forceinline__ void mma16816(float* c, const unsigned* a, const unsigned* b) {
    asm volatile(
        "mma.sync.aligned.m16n8k16.row.col.f32.bf16.bf16.f32 "
        "{%0,%1,%2,%3}, {%4,%5,%6,%7}, {%8,%9}, {%0,%1,%2,%3};"
        : "+f"(c[0]), "+f"(c[1]), "+f"(c[2]), "+f"(c[3])
        : "r"(a[0]), "r"(a[1]), "r"(a[2]), "r"(a[3]), "r"(b[0]), "r"(b[1]));
}

// ---------------- preamble kernels ----------------

// W [K,N] f32 -> Wt [N,K] bf16 (transposing convert)
__global__ void k_tcvt(const float* __restrict__ W, bf16* __restrict__ Wt, int K, int N) {
    __shared__ float tile[32][33];
    int k0 = blockIdx.y * 32, n0 = blockIdx.x * 32;
    int tx = threadIdx.x, ty = threadIdx.y;
    for (int i = ty; i < 32; i += 8)
        tile[i][tx] = W[(size_t)(k0 + i) * N + n0 + tx];
    __syncthreads();
    for (int i = ty; i < 32; i += 8)
        Wt[(size_t)(n0 + i) * K + k0 + tx] = __float2bfloat16(tile[tx][i]);
}

// ss = silu(t) @ Wss + bss. 64 blocks x 512 threads, 8-way k-split.
__global__ __launch_bounds__(512)
void k_ss2(const float* __restrict__ tv,
           const float* __restrict__ Wq, const float* __restrict__ bq,
           const float* __restrict__ Wkv, const float* __restrict__ bkv) {
    __shared__ float st[BZ * H];
    __shared__ float red[8][512];
    int tid = threadIdx.x;
    for (int i = tid; i < BZ * H; i += 512) {
        float v = tv[i];
        st[i] = v / (1.f + __expf(-v));
    }
    __syncthreads();

    int sel = blockIdx.x >> 5;
    int n = ((blockIdx.x & 31) << 6) + (tid & 63);
    int kt = tid >> 6;
    const float* W = sel ? Wkv : Wq;
    const float* bs = sel ? bkv : bq;
    float* o = sel ? g_sskv : g_ssq;

    float acc[BZ];
#pragma unroll
    for (int b = 0; b < BZ; b++) acc[b] = 0.f;
    const float* Wp = W + (size_t)(kt * 128) * H2 + n;
    const float* stp = st + kt * 128;
#pragma unroll 4
    for (int kk = 0; kk < 128; kk++) {
        float w = Wp[(size_t)kk * H2];
#pragma unroll
        for (int b = 0; b < BZ; b++) acc[b] += stp[b * H + kk] * w;
    }
#pragma unroll
    for (int b = 0; b < BZ; b++) red[kt][b * 64 + (tid & 63)] = acc[b];
    __syncthreads();

    int b2 = tid >> 6, c2 = tid & 63;
    float s = 0.f;
#pragma unroll
    for (int k = 0; k < 8; k++) s += red[k][b2 * 64 + c2];
    int n2 = ((blockIdx.x & 31) << 6) + c2;
    o[b2 * H2 + n2] = s + bs[n2];
}

// adaLN: one block per row.
__global__ void k_adaln(const float* __restrict__ x, const float* __restrict__ ss,
                        bf16* __restrict__ o, int L) {
    int r = blockIdx.x;
    int b = r / L;
    const float* xr = x + (size_t)r * H;
    float s = 0.f, s2 = 0.f;
    for (int i = threadIdx.x; i < H; i += blockDim.x) {
        float v = xr[i];
        s += v; s2 += v * v;
    }
    __shared__ float red[64];
#pragma unroll
    for (int off = 16; off; off >>= 1) {
        s  += __shfl_xor_sync(~0u, s, off);
        s2 += __shfl_xor_sync(~0u, s2, off);
    }
    int w = threadIdx.x >> 5, l = threadIdx.x & 31;
    if (l == 0) { red[w] = s; red[32 + w] = s2; }
    __syncthreads();
    int nw = blockDim.x >> 5;
    if (w == 0) {
        s  = (l < nw) ? red[l] : 0.f;
        s2 = (l < nw) ? red[32 + l] : 0.f;
#pragma unroll
        for (int off = 16; off; off >>= 1) {
            s  += __shfl_xor_sync(~0u, s, off);
            s2 += __shfl_xor_sync(~0u, s2, off);
        }
        if (l == 0) { red[0] = s; red[1] = s2; }
    }
    __syncthreads();
    float mu = red[0] / H;
    float var = red[1] / H - mu * mu;
    float rstd = rsqrtf(var + 1e-5f);
    const float* sc = ss + (size_t)b * H2;
    for (int i = threadIdx.x; i < H; i += blockDim.x) {
        float hh = (xr[i] - mu) * rstd;
        o[(size_t)r * H + i] = __float2bfloat16((1.f + sc[i]) * hh + sc[H + i]);
    }
}

// ---------------- mma.sync GEMM (R13, equal-best) ----------------
constexpr int TSTG = 32768;
constexpr int GSMEM = 3 * TSTG;
constexpr int TK = 1024, TT = TK / 64;

__global__ __launch_bounds__(256)
void k_gemm3(const bf16* __restrict__ A, const bf16* __restrict__ Bt,
             float* __restrict__ Cf, bf16* __restrict__ Cb,
             const float* __restrict__ bias, const float* __restrict__ resid,
             int N) {
    extern __shared__ __align__(1024) char smem[];
    unsigned sb = smem_u32(smem);

    int m0 = blockIdx.y * 128, n0 = blockIdx.x * 128;
    int tid = threadIdx.x;
    int wid = tid >> 5, lane = tid & 31;
    int wm = wid >> 2, wn = wid & 3;

    auto load_stage = [&](int slot, int kt) {
        char* base = smem + slot * TSTG;
        int k0 = kt * 64;
#pragma unroll
        for (int i = 0; i < 4; i++) {
            int idx = tid + i * 256;
            int r = idx >> 3, cc = idx & 7;
            cp16(base + sw128(r * 128 + cc * 16),
                 A + (size_t)(m0 + r) * TK + k0 + cc * 8);
        }
#pragma unroll
        for (int i = 0; i < 4; i++) {
            int idx = tid + i * 256;
            int r = idx >> 3, cc = idx & 7;
            cp16(base + 16384 + sw128(r * 128 + cc * 16),
                 Bt + (size_t)(n0 + r) * TK + k0 + cc * 8);
        }
        CP_COMMIT();
    };

    float acc[4][4][4];
#pragma unroll
    for (int i = 0; i < 4; i++)
#pragma unroll
        for (int j = 0; j < 4; j++)
#pragma unroll
            for (int e = 0; e < 4; e++) acc[i][j][e] = 0.f;

    int a_row = ((lane >> 3) & 1) * 8 + (lane & 7);
    int a_chk = lane >> 4;
    int b4_row = ((lane >> 4) & 1) * 8 + (lane & 7);
    int b4_chk = (lane >> 3) & 1;

    load_stage(0, 0);
    load_stage(1, 1);

    for (int t = 0; t < TT; t++) {
        if (t + 1 < TT) { CP_WAIT(1); } else { CP_WAIT(0); }
        __syncthreads();
        if (t + 2 < TT) load_stage((t + 2) % 3, t + 2);
        unsigned As = sb + (t % 3) * TSTG;
        unsigned Bs = As + 16384;
#pragma unroll
        for (int kk = 0; kk < 4; kk++) {
            unsigned a[4][4], b[4][2];
#pragma unroll
            for (int mi = 0; mi < 4; mi++) {
                int mrow = wm * 64 + mi * 16 + a_row;
                ldsm_x4(a[mi][0], a[mi][1], a[mi][2], a[mi][3],
                        As + sw128(mrow * 128 + (kk * 2 + a_chk) * 16));
            }
#pragma unroll
            for (int njp = 0; njp < 2; njp++) {
                int nrow = wn * 32 + njp * 16 + b4_row;
                ldsm_x4(b[njp * 2][0], b[njp * 2][1], b[njp * 2 + 1][0], b[njp * 2 + 1][1],
                        Bs + sw128(nrow * 128 + (kk * 2 + b4_chk) * 16));
            }
#pragma unroll
            for (int mi = 0; mi < 4; mi++)
#pragma unroll
                for (int nj = 0; nj < 4; nj++)
                    mma16816(acc[mi][nj], a[mi], b[nj]);
        }
    }

    // direct register epilogue
    {
        int c_base = wn * 32 + 2 * (lane & 3);
        int r_base = m0 + wm * 64 + (lane >> 2);
#pragma unroll
        for (int nj = 0; nj < 4; nj++) {
            int col = n0 + c_base + nj * 8;
            float2 bv = *(const float2*)&bias[col];
#pragma unroll
            for (int mi = 0; mi < 4; mi++) {
                size_t gi0 = (size_t)(r_base + mi * 16) * N + col;
                size_t gi1 = gi0 + (size_t)8 * N;
                float v0 = acc[mi][nj][0] + bv.x, v1 = acc[mi][nj][1] + bv.y;
                float v2 = acc[mi][nj][2] + bv.x, v3 = acc[mi][nj][3] + bv.y;
                if (Cb) {
                    __nv_bfloat162 h0 = __floats2bfloat162_rn(v0, v1);
                    __nv_bfloat162 h1 = __floats2bfloat162_rn(v2, v3);
                    *(__nv_bfloat162*)&Cb[gi0] = h0;
                    *(__nv_bfloat162*)&Cb[gi1] = h1;
                } else {
                    float2 r0 = *(const float2*)&resid[gi0];
                    float2 r1 = *(const float2*)&resid[gi1];
                    float2 o0; o0.x = v0 + r0.x; o0.y = v1 + r0.y;
                    float2 o1; o1.x = v2 + r1.x; o1.y = v3 + r1.y;
                    *(float2*)&Cf[gi0] = o0;
                    *(float2*)&Cf[gi1] = o1;
                }
            }
        }
    }
}

// ---------------- fused attention v3: 512 threads, QT=64 ----------------
// Grid (4, BH) = 512 CTAs; CTA covers 512 q-rows in 8 tiles of 64.
// K+V resident; S in regs (warp grid 2x8: 32 rows x 64 cols each);
// PV warp grid 4x4 (16 rows x 16 cols each); unnormalized bf16 P.
constexpr int AT_K  = 0;                  // 65536
constexpr int AT_V  = 65536;              // 65536
constexpr int AT_Q  = 131072;             // 2 x 8192
constexpr int AT_P  = 147456;             // 64*520*2 = 66560
constexpr int AT_RM = 214016;             // 64*9*4 = 2304
constexpr int AT_RS = 216320;             // 2304
constexpr int AT3_SMEM = 218624;
constexpr int PSTR = 520;

__global__ __launch_bounds__(512)
void k_attn3(const bf16* __restrict__ Q, const bf16* __restrict__ KV,
             bf16* __restrict__ O) {
    extern __shared__ __align__(1024) char sm[];
    unsigned sb = smem_u32(sm);
    float* red_m = (float*)(sm + AT_RM);
    float* red_s = (float*)(sm + AT_RS);
    bf16*  Pb    = (bf16*)(sm + AT_P);

    int z = blockIdx.y;
    int b = z >> 4, h = z & 15;
    int tid = threadIdx.x, wid = tid >> 5, lane = tid & 31;
    int wr = wid >> 3, wc = wid & 7;        // S stage: 2 x 8
    int mi2 = wid >> 2, njw = wid & 3;      // PV stage: 4 x 4

    const bf16* Kg = KV + (size_t)b * LKV * H2 + h * DH;
    const bf16* Vg = Kg + H;
    const bf16* Qg = Q + ((size_t)b * LQ + blockIdx.x * 512) * H + h * DH;

    // K + V resident
    for (int i = tid; i < LKV * 8; i += 512) {
        int r = i >> 3, c = i & 7;
        cp16(sm + AT_K + sw128(r * 128 + c * 16), Kg + (size_t)r * H2 + c * 8);
        cp16(sm + AT_V + sw128(r * 128 + c * 16), Vg + (size_t)r * H2 + c * 8);
    }
    {   // Q tile 0: 64 rows x 8 chunks = 512
        int r = tid >> 3, c = tid & 7;
        cp16(sm + AT_Q + sw128(r * 128 + c * 16), Qg + (size_t)r * H + c * 8);
    }
    CP_COMMIT();

    int a_row = ((lane >> 3) & 1) * 8 + (lane & 7);
    int a_chk = lane >> 4;
    int b4_row = ((lane >> 4) & 1) * 8 + (lane & 7);
    int b4_chk = (lane >> 3) & 1;
    int r4 = lane >> 2;

    for (int it = 0; it < 8; it++) {
        CP_WAIT(0);
        __syncthreads();
        if (it + 1 < 8) {   // prefetch next Q tile
            int r = tid >> 3, c = tid & 7;
            cp16(sm + AT_Q + ((it + 1) & 1) * 8192 + sw128(r * 128 + c * 16),
                 Qg + (size_t)((it + 1) * 64 + r) * H + c * 8);
            CP_COMMIT();
        }
        unsigned Qs = sb + AT_Q + (it & 1) * 8192;
        unsigned Ks = sb + AT_K;

        // ---- S = Q @ K^T : warp (wr, wc) -> rows [wr*32,+32), cols [wc*64,+64) ----
        float acc[2][8][4];
#pragma unroll
        for (int mi = 0; mi < 2; mi++)
#pragma unroll
            for (int nj = 0; nj < 8; nj++)
#pragma unroll
                for (int e = 0; e < 4; e++) acc[mi][nj][e] = 0.f;
#pragma unroll
        for (int kk = 0; kk < 4; kk++) {
            unsigned a[2][4], bb[8][2];
#pragma unroll
            for (int mi = 0; mi < 2; mi++)
                ldsm_x4(a[mi][0], a[mi][1], a[mi][2], a[mi][3],
                        Qs + sw128((wr * 32 + mi * 16 + a_row) * 128 + (kk * 2 + a_chk) * 16));
#pragma unroll
            for (int njp = 0; njp < 4; njp++) {
                int nrow = wc * 64 + njp * 16 + b4_row;
                ldsm_x4(bb[njp * 2][0], bb[njp * 2][1], bb[njp * 2 + 1][0], bb[njp * 2 + 1][1],
                        Ks + sw128(nrow * 128 + (kk * 2 + b4_chk) * 16));
            }
#pragma unroll
            for (int mi = 0; mi < 2; mi++)
#pragma unroll
                for (int nj = 0; nj < 8; nj++)
                    mma16816(acc[mi][nj], a[mi], bb[nj]);
        }

        // ---- softmax part 1: per-warp row max ----
#pragma unroll
        for (int mi = 0; mi < 2; mi++)
#pragma unroll
            for (int hh = 0; hh < 2; hh++) {
                float m = -FLT_MAX;
#pragma unroll
                for (int nj = 0; nj < 8; nj++) {
                    m = fmaxf(m, acc[mi][nj][2 * hh]);
                    m = fmaxf(m, acc[mi][nj][2 * hh + 1]);
                }
                m = fmaxf(m, __shfl_xor_sync(~0u, m, 1));
                m = fmaxf(m, __shfl_xor_sync(~0u, m, 2));
                if ((lane & 3) == 0)
                    red_m[(wr * 32 + mi * 16 + hh * 8 + r4) * 9 + wc] = m;
            }
        __syncthreads();

        // ---- part 2: global max, exp (x 1/8), unnormalized P, partial sums ----
#pragma unroll
        for (int mi = 0; mi < 2; mi++)
#pragma unroll
            for (int hh = 0; hh < 2; hh++) {
                int row = wr * 32 + mi * 16 + hh * 8 + r4;
                float g = red_m[row * 9];
#pragma unroll
                for (int w = 1; w < 8; w++) g = fmaxf(g, red_m[row * 9 + w]);
                float sum = 0.f;
#pragma unroll
                for (int nj = 0; nj < 8; nj++) {
                    float e0 = __expf((acc[mi][nj][2 * hh] - g) * 0.125f);
                    float e1 = __expf((acc[mi][nj][2 * hh + 1] - g) * 0.125f);
                    sum += e0 + e1;
                    __nv_bfloat162 p = __floats2bfloat162_rn(e0, e1);
                    *(__nv_bfloat162*)(Pb + row * PSTR + wc * 64 + nj * 8 + 2 * (lane & 3)) = p;
                }
                sum += __shfl_xor_sync(~0u, sum, 1);
                sum += __shfl_xor_sync(~0u, sum, 2);
                if ((lane & 3) == 0) red_s[row * 9 + wc] = sum;
            }
        __syncthreads();

        // ---- O = P @ V : warp (mi2, njw) -> rows [mi2*16,+16), cols [njw*16,+16) ----
        float oacc[2][4];
#pragma unroll
        for (int t = 0; t < 2; t++)
#pragma unroll
            for (int e = 0; e < 4; e++) oacc[t][e] = 0.f;
        unsigned Vs = sb + AT_V;
        unsigned Pa = sb + AT_P;
#pragma unroll 4
        for (int kc = 0; kc < 32; kc++) {
            unsigned a[4], bb[2][2];
            ldsm_x4(a[0], a[1], a[2], a[3],
                    Pa + (mi2 * 16 + a_row) * (PSTR * 2) + (kc * 2 + a_chk) * 16);
            ldsm_x4t(bb[0][0], bb[0][1], bb[1][0], bb[1][1],
                     Vs + sw128((kc * 16 + (lane & 15)) * 128 + njw * 32 + (lane >> 4) * 16));
#pragma unroll
            for (int t = 0; t < 2; t++) mma16816(oacc[t], a, bb[t]);
        }

        // ---- epilogue: 1/rowsum scale, write O ----
        int row0 = mi2 * 16 + r4, row1 = row0 + 8;
        float s0 = 0.f, s1 = 0.f;
#pragma unroll
        for (int w = 0; w < 8; w++) { s0 += red_s[row0 * 9 + w]; s1 += red_s[row1 * 9 + w]; }
        float inv0 = 1.f / s0, inv1 = 1.f / s1;
        size_t ob = (size_t)b * LQ + blockIdx.x * 512 + it * 64;
#pragma unroll
        for (int t = 0; t < 2; t++) {
            int col = njw * 16 + t * 8 + 2 * (lane & 3);
            __nv_bfloat162 p0 = __floats2bfloat162_rn(oacc[t][0] * inv0, oacc[t][1] * inv0);
            __nv_bfloat162 p1 = __floats2bfloat162_rn(oacc[t][2] * inv1, oacc[t][3] * inv1);
            *(__nv_bfloat162*)&O[(ob + row0) * H + h * DH + col] = p0;
            *(__nv_bfloat162*)&O[(ob + row1) * H + h * DH + col] = p1;
        }
    }
}

// ---------------- launch ----------------

extern "C" void kernel_launch(void* const* d_in, const int* in_sizes, int n_in,
                              void* d_out, int out_size) {
    (void)in_sizes; (void)n_in; (void)out_size;
    const float* x_q    = (const float*)d_in[0];
    const float* x_kv   = (const float*)d_in[1];
    const float* t_vec  = (const float*)d_in[2];
    const float* Wq     = (const float*)d_in[3];
    const float* bq     = (const float*)d_in[4];
    const float* Wkv    = (const float*)d_in[5];
    const float* bkv    = (const float*)d_in[6];
    const float* Wp     = (const float*)d_in[7];
    const float* bp     = (const float*)d_in[8];
    const float* Wss_q  = (const float*)d_in[9];
    const float* bss_q  = (const float*)d_in[10];
    const float* Wss_kv = (const float*)d_in[11];
    const float* bss_kv = (const float*)d_in[12];

    void *p_xq, *p_xkv, *p_q, *p_kv, *p_ao, *p_wq, *p_wkv, *p_wp, *p_ssq, *p_sskv;
    cudaGetSymbolAddress(&p_xq, g_xq);
    cudaGetSymbolAddress(&p_xkv, g_xkv);
    cudaGetSymbolAddress(&p_q, g_q);
    cudaGetSymbolAddress(&p_kv, g_kv);
    cudaGetSymbolAddress(&p_ao, g_ao);
    cudaGetSymbolAddress(&p_wq, g_wq);
    cudaGetSymbolAddress(&p_wkv, g_wkv);
    cudaGetSymbolAddress(&p_wp, g_wp);
    cudaGetSymbolAddress(&p_ssq, g_ssq);
    cudaGetSymbolAddress(&p_sskv, g_sskv);

    cudaFuncSetAttribute(k_gemm3, cudaFuncAttributeMaxDynamicSharedMemorySize, GSMEM);
    cudaFuncSetAttribute(k_attn3, cudaFuncAttributeMaxDynamicSharedMemorySize, AT3_SMEM);

    k_tcvt<<<dim3(H / 32, H / 32), dim3(32, 8)>>>(Wq, (bf16*)p_wq, H, H);       // 1
    k_ss2<<<64, 512>>>(t_vec, Wss_q, bss_q, Wss_kv, bss_kv);                    // 2
    k_adaln<<<BZ * LQ, 256>>>(x_q, (const float*)p_ssq, (bf16*)p_xq, LQ);       // 3
    k_gemm3<<<dim3(H / 128, BZ * LQ / 128), 256, GSMEM>>>(                      // 4 <- profiled
        (const bf16*)p_xq, (const bf16*)p_wq, nullptr, (bf16*)p_q, bq, nullptr, H);

    k_tcvt<<<dim3(H2 / 32, H / 32), dim3(32, 8)>>>(Wkv, (bf16*)p_wkv, H, H2);   // 5
    k_adaln<<<BZ * LKV, 256>>>(x_kv, (const float*)p_sskv, (bf16*)p_xkv, LKV);  // 6
    k_gemm3<<<dim3(H2 / 128, BZ * LKV / 128), 256, GSMEM>>>(                    // 7
        (const bf16*)p_xkv, (const bf16*)p_wkv, nullptr, (bf16*)p_kv, bkv, nullptr, H2);

    k_attn3<<<dim3(4, BH), 512, AT3_SMEM>>>(                                    // 8
        (const bf16*)p_q, (const bf16*)p_kv, (bf16*)p_ao);

    k_tcvt<<<dim3(H / 32, H / 32), dim3(32, 8)>>>(Wp, (bf16*)p_wp, H, H);       // 9
    k_gemm3<<<dim3(H / 128, BZ * LQ / 128), 256, GSMEM>>>(                      // 10
        (const bf16*)p_ao, (const bf16*)p_wp, (float*)d_out, nullptr, bp, x_q, H);
}

// round 17
// speedup vs baseline: 1.1469x; 1.1469x over previous
#include <cuda_runtime.h>
#include <cuda_bf16.h>
#include <cfloat>

typedef __nv_bfloat16 bf16;

// Problem dims
constexpr int BZ = 8, LQ = 2048, LKV = 512, H = 1024, H2 = 2048, NH = 16, DH = 64, BH = BZ * NH;
constexpr size_t NQ  = (size_t)BZ * LQ * H;
constexpr size_t NKV = (size_t)BZ * LKV * H;

// Scratch (device globals: allocation-free per harness rules)
__device__ bf16  g_xq[NQ];
__device__ bf16  g_xkv[NKV];
__device__ bf16  g_q[NQ];
__device__ bf16  g_kv[2 * NKV];
__device__ bf16  g_ao[NQ];
__device__ bf16  g_wq[H * H];      // transposed: [N=H, K=H]
__device__ bf16  g_wkv[H2 * H];    // transposed: [N=2H, K=H]
__device__ bf16  g_wp[H * H];      // transposed
__device__ float g_ssq[BZ * H2];
__device__ float g_sskv[BZ * H2];

// ---------------- low-level helpers ----------------
__device__ __forceinline__ unsigned smem_u32(const void* p) {
    return (unsigned)__cvta_generic_to_shared(p);
}
__device__ __forceinline__ void cp16(void* s, const void* g) {
    unsigned sa = smem_u32(s);
    asm volatile("cp.async.cg.shared.global [%0], [%1], 16;\n" :: "r"(sa), "l"(g));
}
#define CP_COMMIT()  asm volatile("cp.async.commit_group;\n")
#define CP_WAIT(N)   asm volatile("cp.async.wait_group %0;\n" :: "n"(N))

__device__ __forceinline__ unsigned sw128(unsigned x) { return x ^ ((x >> 3) & 0x70); }

__device__ __forceinline__ void ldsm_x4(unsigned& r0, unsigned& r1, unsigned& r2, unsigned& r3,
                                        unsigned addr) {
    asm volatile("ldmatrix.sync.aligned.m8n8.x4.shared.b16 {%0,%1,%2,%3}, [%4];"
                 : "=r"(r0), "=r"(r1), "=r"(r2), "=r"(r3) : "r"(addr));
}
__device__ __forceinline__ void ldsm_x4t(unsigned& r0, unsigned& r1, unsigned& r2, unsigned& r3,
                                         unsigned addr) {
    asm volatile("ldmatrix.sync.aligned.m8n8.x4.trans.shared.b16 {%0,%1,%2,%3}, [%4];"
                 : "=r"(r0), "=r"(r1), "=r"(r2), "=r"(r3) : "r"(addr));
}
__device__ __forceinline__ void mma16816(float* c, const unsigned* a, const unsigned* b) {
    asm volatile(
        "mma.sync.aligned.m16n8k16.row.col.f32.bf16.bf16.f32 "
        "{%0,%1,%2,%3}, {%4,%5,%6,%7}, {%8,%9}, {%0,%1,%2,%3};"
        : "+f"(c[0]), "+f"(c[1]), "+f"(c[2]), "+f"(c[3])
        : "r"(a[0]), "r"(a[1]), "r"(a[2]), "r"(a[3]), "r"(b[0]), "r"(b[1]));
}
__device__ __forceinline__ unsigned packbf2(float x, float y) {
    __nv_bfloat162 p = __floats2bfloat162_rn(x, y);
    return *(unsigned*)&p;
}

// ---------------- preamble kernels ----------------

// W [K,N] f32 -> Wt [N,K] bf16 (transposing convert)
__global__ void k_tcvt(const float* __restrict__ W, bf16* __restrict__ Wt, int K, int N) {
    __shared__ float tile[32][33];
    int k0 = blockIdx.y * 32, n0 = blockIdx.x * 32;
    int tx = threadIdx.x, ty = threadIdx.y;
    for (int i = ty; i < 32; i += 8)
        tile[i][tx] = W[(size_t)(k0 + i) * N + n0 + tx];
    __syncthreads();
    for (int i = ty; i < 32; i += 8)
        Wt[(size_t)(n0 + i) * K + k0 + tx] = __float2bfloat16(tile[tx][i]);
}

// ss = silu(t) @ Wss + bss. 64 blocks x 512 threads, 8-way k-split.
__global__ __launch_bounds__(512)
void k_ss2(const float* __restrict__ tv,
           const float* __restrict__ Wq, const float* __restrict__ bq,
           const float* __restrict__ Wkv, const float* __restrict__ bkv) {
    __shared__ float st[BZ * H];
    __shared__ float red[8][512];
    int tid = threadIdx.x;
    for (int i = tid; i < BZ * H; i += 512) {
        float v = tv[i];
        st[i] = v / (1.f + __expf(-v));
    }
    __syncthreads();

    int sel = blockIdx.x >> 5;
    int n = ((blockIdx.x & 31) << 6) + (tid & 63);
    int kt = tid >> 6;
    const float* W = sel ? Wkv : Wq;
    const float* bs = sel ? bkv : bq;
    float* o = sel ? g_sskv : g_ssq;

    float acc[BZ];
#pragma unroll
    for (int b = 0; b < BZ; b++) acc[b] = 0.f;
    const float* Wp = W + (size_t)(kt * 128) * H2 + n;
    const float* stp = st + kt * 128;
#pragma unroll 4
    for (int kk = 0; kk < 128; kk++) {
        float w = Wp[(size_t)kk * H2];
#pragma unroll
        for (int b = 0; b < BZ; b++) acc[b] += stp[b * H + kk] * w;
    }
#pragma unroll
    for (int b = 0; b < BZ; b++) red[kt][b * 64 + (tid & 63)] = acc[b];
    __syncthreads();

    int b2 = tid >> 6, c2 = tid & 63;
    float s = 0.f;
#pragma unroll
    for (int k = 0; k < 8; k++) s += red[k][b2 * 64 + c2];
    int n2 = ((blockIdx.x & 31) << 6) + c2;
    o[b2 * H2 + n2] = s + bs[n2];
}

// adaLN: one block per row.
__global__ void k_adaln(const float* __restrict__ x, const float* __restrict__ ss,
                        bf16* __restrict__ o, int L) {
    int r = blockIdx.x;
    int b = r / L;
    const float* xr = x + (size_t)r * H;
    float s = 0.f, s2 = 0.f;
    for (int i = threadIdx.x; i < H; i += blockDim.x) {
        float v = xr[i];
        s += v; s2 += v * v;
    }
    __shared__ float red[64];
#pragma unroll
    for (int off = 16; off; off >>= 1) {
        s  += __shfl_xor_sync(~0u, s, off);
        s2 += __shfl_xor_sync(~0u, s2, off);
    }
    int w = threadIdx.x >> 5, l = threadIdx.x & 31;
    if (l == 0) { red[w] = s; red[32 + w] = s2; }
    __syncthreads();
    int nw = blockDim.x >> 5;
    if (w == 0) {
        s  = (l < nw) ? red[l] : 0.f;
        s2 = (l < nw) ? red[32 + l] : 0.f;
#pragma unroll
        for (int off = 16; off; off >>= 1) {
            s  += __shfl_xor_sync(~0u, s, off);
            s2 += __shfl_xor_sync(~0u, s2, off);
        }
        if (l == 0) { red[0] = s; red[1] = s2; }
    }
    __syncthreads();
    float mu = red[0] / H;
    float var = red[1] / H - mu * mu;
    float rstd = rsqrtf(var + 1e-5f);
    const float* sc = ss + (size_t)b * H2;
    for (int i = threadIdx.x; i < H; i += blockDim.x) {
        float hh = (xr[i] - mu) * rstd;
        o[(size_t)r * H + i] = __float2bfloat16((1.f + sc[i]) * hh + sc[H + i]);
    }
}

// ---------------- mma.sync GEMM (equal-best, frozen) ----------------
constexpr int TSTG = 32768;
constexpr int GSMEM = 3 * TSTG;
constexpr int TK = 1024, TT = TK / 64;

__global__ __launch_bounds__(256)
void k_gemm3(const bf16* __restrict__ A, const bf16* __restrict__ Bt,
             float* __restrict__ Cf, bf16* __restrict__ Cb,
             const float* __restrict__ bias, const float* __restrict__ resid,
             int N) {
    extern __shared__ __align__(1024) char smem[];
    unsigned sb = smem_u32(smem);

    int m0 = blockIdx.y * 128, n0 = blockIdx.x * 128;
    int tid = threadIdx.x;
    int wid = tid >> 5, lane = tid & 31;
    int wm = wid >> 2, wn = wid & 3;

    auto load_stage = [&](int slot, int kt) {
        char* base = smem + slot * TSTG;
        int k0 = kt * 64;
#pragma unroll
        for (int i = 0; i < 4; i++) {
            int idx = tid + i * 256;
            int r = idx >> 3, cc = idx & 7;
            cp16(base + sw128(r * 128 + cc * 16),
                 A + (size_t)(m0 + r) * TK + k0 + cc * 8);
        }
#pragma unroll
        for (int i = 0; i < 4; i++) {
            int idx = tid + i * 256;
            int r = idx >> 3, cc = idx & 7;
            cp16(base + 16384 + sw128(r * 128 + cc * 16),
                 Bt + (size_t)(n0 + r) * TK + k0 + cc * 8);
        }
        CP_COMMIT();
    };

    float acc[4][4][4];
#pragma unroll
    for (int i = 0; i < 4; i++)
#pragma unroll
        for (int j = 0; j < 4; j++)
#pragma unroll
            for (int e = 0; e < 4; e++) acc[i][j][e] = 0.f;

    int a_row = ((lane >> 3) & 1) * 8 + (lane & 7);
    int a_chk = lane >> 4;
    int b4_row = ((lane >> 4) & 1) * 8 + (lane & 7);
    int b4_chk = (lane >> 3) & 1;

    load_stage(0, 0);
    load_stage(1, 1);

    for (int t = 0; t < TT; t++) {
        if (t + 1 < TT) { CP_WAIT(1); } else { CP_WAIT(0); }
        __syncthreads();
        if (t + 2 < TT) load_stage((t + 2) % 3, t + 2);
        unsigned As = sb + (t % 3) * TSTG;
        unsigned Bs = As + 16384;
#pragma unroll
        for (int kk = 0; kk < 4; kk++) {
            unsigned a[4][4], b[4][2];
#pragma unroll
            for (int mi = 0; mi < 4; mi++) {
                int mrow = wm * 64 + mi * 16 + a_row;
                ldsm_x4(a[mi][0], a[mi][1], a[mi][2], a[mi][3],
                        As + sw128(mrow * 128 + (kk * 2 + a_chk) * 16));
            }
#pragma unroll
            for (int njp = 0; njp < 2; njp++) {
                int nrow = wn * 32 + njp * 16 + b4_row;
                ldsm_x4(b[njp * 2][0], b[njp * 2][1], b[njp * 2 + 1][0], b[njp * 2 + 1][1],
                        Bs + sw128(nrow * 128 + (kk * 2 + b4_chk) * 16));
            }
#pragma unroll
            for (int mi = 0; mi < 4; mi++)
#pragma unroll
                for (int nj = 0; nj < 4; nj++)
                    mma16816(acc[mi][nj], a[mi], b[nj]);
        }
    }

    // direct register epilogue
    {
        int c_base = wn * 32 + 2 * (lane & 3);
        int r_base = m0 + wm * 64 + (lane >> 2);
#pragma unroll
        for (int nj = 0; nj < 4; nj++) {
            int col = n0 + c_base + nj * 8;
            float2 bv = *(const float2*)&bias[col];
#pragma unroll
            for (int mi = 0; mi < 4; mi++) {
                size_t gi0 = (size_t)(r_base + mi * 16) * N + col;
                size_t gi1 = gi0 + (size_t)8 * N;
                float v0 = acc[mi][nj][0] + bv.x, v1 = acc[mi][nj][1] + bv.y;
                float v2 = acc[mi][nj][2] + bv.x, v3 = acc[mi][nj][3] + bv.y;
                if (Cb) {
                    __nv_bfloat162 h0 = __floats2bfloat162_rn(v0, v1);
                    __nv_bfloat162 h1 = __floats2bfloat162_rn(v2, v3);
                    *(__nv_bfloat162*)&Cb[gi0] = h0;
                    *(__nv_bfloat162*)&Cb[gi1] = h1;
                } else {
                    float2 r0 = *(const float2*)&resid[gi0];
                    float2 r1 = *(const float2*)&resid[gi1];
                    float2 o0; o0.x = v0 + r0.x; o0.y = v1 + r0.y;
                    float2 o1; o1.x = v2 + r1.x; o1.y = v3 + r1.y;
                    *(float2*)&Cf[gi0] = o0;
                    *(float2*)&Cf[gi1] = o1;
                }
            }
        }
    }
}

// ---------------- fused attention v4: warp-autonomous FA2 ----------------
// Grid (8, BH), 512 threads. Each warp owns 16 q-rows x full KV.
// Online softmax; P stays in registers (S C-frag == PV A-frag layout).
// NO block syncs after the initial load. K+V+Q resident in smem.
constexpr int A4_K = 0;          // 512*128 = 65536
constexpr int A4_V = 65536;      // 65536
constexpr int A4_Q = 131072;     // 256*128 = 32768
constexpr int AT4_SMEM = 163840;

__global__ __launch_bounds__(512)
void k_attn4(const bf16* __restrict__ Q, const bf16* __restrict__ KV,
             bf16* __restrict__ O) {
    extern __shared__ __align__(1024) char sm[];
    unsigned sb = smem_u32(sm);

    int z = blockIdx.y;
    int b = z >> 4, h = z & 15;
    int tid = threadIdx.x, wid = tid >> 5, lane = tid & 31;

    const bf16* Kg = KV + (size_t)b * LKV * H2 + h * DH;
    const bf16* Vg = Kg + H;
    const bf16* Qg = Q + ((size_t)b * LQ + blockIdx.x * 256) * H + h * DH;

    // load K + V + Q (this CTA's 256 q rows), all resident
    for (int i = tid; i < LKV * 8; i += 512) {
        int r = i >> 3, c = i & 7;
        cp16(sm + A4_K + sw128(r * 128 + c * 16), Kg + (size_t)r * H2 + c * 8);
        cp16(sm + A4_V + sw128(r * 128 + c * 16), Vg + (size_t)r * H2 + c * 8);
    }
    for (int i = tid; i < 256 * 8; i += 512) {
        int r = i >> 3, c = i & 7;
        cp16(sm + A4_Q + sw128(r * 128 + c * 16), Qg + (size_t)r * H + c * 8);
    }
    CP_COMMIT();
    CP_WAIT(0);
    __syncthreads();   // only block sync in the kernel

    int a_row = ((lane >> 3) & 1) * 8 + (lane & 7);
    int a_chk = lane >> 4;
    int b4_row = ((lane >> 4) & 1) * 8 + (lane & 7);
    int b4_chk = (lane >> 3) & 1;
    int r4 = lane >> 2;

    unsigned Qs = sb + A4_Q + wid * 2048;   // warp's 16 q rows (16*128B)
    unsigned Ks = sb + A4_K;
    unsigned Vs = sb + A4_V;

    float oacc[8][4];
#pragma unroll
    for (int nj = 0; nj < 8; nj++)
#pragma unroll
        for (int e = 0; e < 4; e++) oacc[nj][e] = 0.f;
    float m0v = -FLT_MAX, m1v = -FLT_MAX, l0 = 0.f, l1 = 0.f;

    for (int c = 0; c < 8; c++) {          // KV chunks of 64
        // ---- S = Q(16x64) @ K_chunk^T(64x64) ----
        float sacc[8][4];
#pragma unroll
        for (int nj = 0; nj < 8; nj++)
#pragma unroll
            for (int e = 0; e < 4; e++) sacc[nj][e] = 0.f;
#pragma unroll
        for (int kk = 0; kk < 4; kk++) {
            unsigned a[4], bb[8][2];
            ldsm_x4(a[0], a[1], a[2], a[3],
                    Qs + sw128(a_row * 128 + (kk * 2 + a_chk) * 16));
#pragma unroll
            for (int njp = 0; njp < 4; njp++) {
                int nrow = c * 64 + njp * 16 + b4_row;
                ldsm_x4(bb[njp * 2][0], bb[njp * 2][1], bb[njp * 2 + 1][0], bb[njp * 2 + 1][1],
                        Ks + sw128(nrow * 128 + (kk * 2 + b4_chk) * 16));
            }
#pragma unroll
            for (int nj = 0; nj < 8; nj++)
                mma16816(sacc[nj], a, bb[nj]);
        }

        // ---- online softmax update (in-warp only; rows r4 and r4+8) ----
        float mc0 = -FLT_MAX, mc1 = -FLT_MAX;
#pragma unroll
        for (int nj = 0; nj < 8; nj++) {
            mc0 = fmaxf(mc0, fmaxf(sacc[nj][0], sacc[nj][1]));
            mc1 = fmaxf(mc1, fmaxf(sacc[nj][2], sacc[nj][3]));
        }
        mc0 = fmaxf(mc0, __shfl_xor_sync(~0u, mc0, 1));
        mc0 = fmaxf(mc0, __shfl_xor_sync(~0u, mc0, 2));
        mc1 = fmaxf(mc1, __shfl_xor_sync(~0u, mc1, 1));
        mc1 = fmaxf(mc1, __shfl_xor_sync(~0u, mc1, 2));
        mc0 *= 0.125f; mc1 *= 0.125f;
        float mn0 = fmaxf(m0v, mc0), mn1 = fmaxf(m1v, mc1);
        float f0 = __expf(m0v - mn0), f1 = __expf(m1v - mn1);
        m0v = mn0; m1v = mn1;

        unsigned pa[4][4];
        float sum0 = 0.f, sum1 = 0.f;
#pragma unroll
        for (int j = 0; j < 4; j++) {
            float e00 = __expf(fmaf(sacc[2 * j][0],     0.125f, -mn0));
            float e01 = __expf(fmaf(sacc[2 * j][1],     0.125f, -mn0));
            float e02 = __expf(fmaf(sacc[2 * j][2],     0.125f, -mn1));
            float e03 = __expf(fmaf(sacc[2 * j][3],     0.125f, -mn1));
            float e10 = __expf(fmaf(sacc[2 * j + 1][0], 0.125f, -mn0));
            float e11 = __expf(fmaf(sacc[2 * j + 1][1], 0.125f, -mn0));
            float e12 = __expf(fmaf(sacc[2 * j + 1][2], 0.125f, -mn1));
            float e13 = __expf(fmaf(sacc[2 * j + 1][3], 0.125f, -mn1));
            sum0 += e00 + e01 + e10 + e11;
            sum1 += e02 + e03 + e12 + e13;
            pa[j][0] = packbf2(e00, e01);   // row r4,   k 0..7  of 16-chunk j
            pa[j][1] = packbf2(e02, e03);   // row r4+8, k 0..7
            pa[j][2] = packbf2(e10, e11);   // row r4,   k 8..15
            pa[j][3] = packbf2(e12, e13);   // row r4+8, k 8..15
        }
        sum0 += __shfl_xor_sync(~0u, sum0, 1);
        sum0 += __shfl_xor_sync(~0u, sum0, 2);
        sum1 += __shfl_xor_sync(~0u, sum1, 1);
        sum1 += __shfl_xor_sync(~0u, sum1, 2);
        l0 = l0 * f0 + sum0;
        l1 = l1 * f1 + sum1;

        // rescale O
#pragma unroll
        for (int nj = 0; nj < 8; nj++) {
            oacc[nj][0] *= f0; oacc[nj][1] *= f0;
            oacc[nj][2] *= f1; oacc[nj][3] *= f1;
        }

        // ---- O += P(16x64) @ V_chunk(64x64), A-frags from registers ----
#pragma unroll
        for (int j = 0; j < 4; j++) {
#pragma unroll
            for (int njv = 0; njv < 4; njv++) {
                unsigned bt[4];
                ldsm_x4t(bt[0], bt[1], bt[2], bt[3],
                         Vs + sw128((c * 64 + j * 16 + (lane & 15)) * 128
                                    + njv * 32 + (lane >> 4) * 16));
                mma16816(oacc[njv * 2],     pa[j], &bt[0]);
                mma16816(oacc[njv * 2 + 1], pa[j], &bt[2]);
            }
        }
    }

    // ---- finalize: O /= l, write out ----
    float inv0 = 1.f / l0, inv1 = 1.f / l1;
    size_t orow = (size_t)b * LQ + blockIdx.x * 256 + wid * 16;
#pragma unroll
    for (int nj = 0; nj < 8; nj++) {
        int col = h * DH + nj * 8 + 2 * (lane & 3);
        __nv_bfloat162 p0 = __floats2bfloat162_rn(oacc[nj][0] * inv0, oacc[nj][1] * inv0);
        __nv_bfloat162 p1 = __floats2bfloat162_rn(oacc[nj][2] * inv1, oacc[nj][3] * inv1);
        *(__nv_bfloat162*)&O[(orow + r4) * H + col] = p0;
        *(__nv_bfloat162*)&O[(orow + r4 + 8) * H + col] = p1;
    }
}

// ---------------- launch ----------------

extern "C" void kernel_launch(void* const* d_in, const int* in_sizes, int n_in,
                              void* d_out, int out_size) {
    (void)in_sizes; (void)n_in; (void)out_size;
    const float* x_q    = (const float*)d_in[0];
    const float* x_kv   = (const float*)d_in[1];
    const float* t_vec  = (const float*)d_in[2];
    const float* Wq     = (const float*)d_in[3];
    const float* bq     = (const float*)d_in[4];
    const float* Wkv    = (const float*)d_in[5];
    const float* bkv    = (const float*)d_in[6];
    const float* Wp     = (const float*)d_in[7];
    const float* bp     = (const float*)d_in[8];
    const float* Wss_q  = (const float*)d_in[9];
    const float* bss_q  = (const float*)d_in[10];
    const float* Wss_kv = (const float*)d_in[11];
    const float* bss_kv = (const float*)d_in[12];

    void *p_xq, *p_xkv, *p_q, *p_kv, *p_ao, *p_wq, *p_wkv, *p_wp, *p_ssq, *p_sskv;
    cudaGetSymbolAddress(&p_xq, g_xq);
    cudaGetSymbolAddress(&p_xkv, g_xkv);
    cudaGetSymbolAddress(&p_q, g_q);
    cudaGetSymbolAddress(&p_kv, g_kv);
    cudaGetSymbolAddress(&p_ao, g_ao);
    cudaGetSymbolAddress(&p_wq, g_wq);
    cudaGetSymbolAddress(&p_wkv, g_wkv);
    cudaGetSymbolAddress(&p_wp, g_wp);
    cudaGetSymbolAddress(&p_ssq, g_ssq);
    cudaGetSymbolAddress(&p_sskv, g_sskv);

    cudaFuncSetAttribute(k_gemm3, cudaFuncAttributeMaxDynamicSharedMemorySize, GSMEM);
    cudaFuncSetAttribute(k_attn4, cudaFuncAttributeMaxDynamicSharedMemorySize, AT4_SMEM);

    k_tcvt<<<dim3(H / 32, H / 32), dim3(32, 8)>>>(Wq, (bf16*)p_wq, H, H);       // 1
    k_ss2<<<64, 512>>>(t_vec, Wss_q, bss_q, Wss_kv, bss_kv);                    // 2
    k_adaln<<<BZ * LQ, 256>>>(x_q, (const float*)p_ssq, (bf16*)p_xq, LQ);       // 3
    k_gemm3<<<dim3(H / 128, BZ * LQ / 128), 256, GSMEM>>>(                      // 4 <- profiled
        (const bf16*)p_xq, (const bf16*)p_wq, nullptr, (bf16*)p_q, bq, nullptr, H);

    k_tcvt<<<dim3(H2 / 32, H / 32), dim3(32, 8)>>>(Wkv, (bf16*)p_wkv, H, H2);   // 5
    k_adaln<<<BZ * LKV, 256>>>(x_kv, (const float*)p_sskv, (bf16*)p_xkv, LKV);  // 6
    k_gemm3<<<dim3(H2 / 128, BZ * LKV / 128), 256, GSMEM>>>(                    // 7
        (const bf16*)p_xkv, (const bf16*)p_wkv, nullptr, (bf16*)p_kv, bkv, nullptr, H2);

    k_attn4<<<dim3(8, BH), 512, AT4_SMEM>>>(                                    // 8
        (const bf16*)p_q, (const bf16*)p_kv, (bf16*)p_ao);

    k_tcvt<<<dim3(H / 32, H / 32), dim3(32, 8)>>>(Wp, (bf16*)p_wp, H, H);       // 9
    k_gemm3<<<dim3(H / 128, BZ * LQ / 128), 256, GSMEM>>>(                      // 10
        (const bf16*)p_ao, (const bf16*)p_wp, (float*)d_out, nullptr, bp, x_q, H);
}